// round 8
// baseline (speedup 1.0000x reference)
#include <cuda_runtime.h>

#define NPTS    4096
#define BATCH   4
#define TPB     256
#define ITILE   2
#define TILE    512                    // square tile side
#define T       (NPTS / TILE)          // 8
#define JSUB    256                    // smem sub-tile width
#define NSYM    (T * (T + 1) / 2)      // 36
#define NCROSS  (T * T)                // 64
#define BPB     (2 * NSYM + NCROSS)    // 136
#define NBLOCKS (BPB * BATCH)          // 544

// sqrt(log2(e)): p = x*SCALE  =>  p_i.p_j = log2(e) * x_i.x_j
#define COORD_SCALE 1.2011224087864498f

__device__ float g_partials[NBLOCKS];
__device__ unsigned int g_count = 0;

typedef unsigned long long ull;

__device__ __forceinline__ ull pack2(float lo, float hi) {
    ull r;
    asm("mov.b64 %0, {%1, %2};" : "=l"(r) : "f"(lo), "f"(hi));
    return r;
}
__device__ __forceinline__ void unpack2(ull v, float& lo, float& hi) {
    asm("mov.b64 {%0, %1}, %2;" : "=f"(lo), "=f"(hi) : "l"(v));
}
__device__ __forceinline__ ull fma2(ull a, ull b, ull c) {
    ull d;
    asm("fma.rn.f32x2 %0, %1, %2, %3;" : "=l"(d) : "l"(a), "l"(b), "l"(c));
    return d;
}
__device__ __forceinline__ ull mul2(ull a, ull b) {
    ull d;
    asm("mul.rn.f32x2 %0, %1, %2;" : "=l"(d) : "l"(a), "l"(b));
    return d;
}
__device__ __forceinline__ float ex2(float x) {
    float r;
    asm("ex2.approx.ftz.f32 %0, %1;" : "=f"(r) : "f"(x));
    return r;
}

// j-tile layout: per j-pair (2 adjacent j's), 3 float4s (48 bytes):
//   [0] = {qx_e, qx_o, qy_e, qy_o}
//   [1] = {qz_e, qz_o, mx_e, mx_o}
//   [2] = {my_e, my_o, mz_e, mz_o}
// m = n_j * 2^{c_j} (exponent constants folded into normals)

__global__ void __launch_bounds__(TPB, 4)
varifold_fused(const float* __restrict__ xyz1,
               const float* __restrict__ xyz2,
               const float* __restrict__ nor1,
               const float* __restrict__ nor2,
               float* __restrict__ out)
{
    // +3 float4 padding so the software-pipeline prefetch past the end is safe
    __shared__ __align__(16) float4 sb[(JSUB / 2) * 3 + 3];
    __shared__ float warpsum[TPB / 32];

    const int tid = threadIdx.x;
    const int b   = blockIdx.y;

    // ---- decode block -> (term, ti, tj, weight) ----
    int idx = blockIdx.x;
    int term, ti, tj;
    float w;
    if (idx < 2 * NSYM) {
        term = (idx < NSYM) ? 0 : 1;
        int k = (idx < NSYM) ? idx : idx - NSYM;
        ti = 0;
        while (k >= T - ti) { k -= T - ti; ti++; }
        tj = ti + k;
        w = (ti == tj) ? 1.0f : 2.0f;   // symmetric: off-diag counted twice
    } else {
        term = 2;
        const int q = idx - 2 * NSYM;
        ti = q >> 3;                    // T == 8
        tj = q & (T - 1);
        w = -2.0f;
    }

    const float* xa; const float* xb; const float* na; const float* nb;
    if (term == 0)      { xa = xyz1; xb = xyz1; na = nor1; nb = nor1; }
    else if (term == 1) { xa = xyz2; xb = xyz2; na = nor2; nb = nor2; }
    else                { xa = xyz1; xb = xyz2; na = nor1; nb = nor2; }

    const long boff = (long)b * NPTS * 3;
    xa += boff; xb += boff; na += boff; nb += boff;

    // ---- register-resident i points: p_i and n'_i = n_i * 2^{c_i} ----
    ull px[ITILE], py[ITILE], pz[ITILE];
    ull nx[ITILE], ny[ITILE], nz[ITILE], acc[ITILE];
    #pragma unroll
    for (int t = 0; t < ITILE; t++) {
        const int i = ti * TILE + t * TPB + tid;
        const float ax = xa[i * 3 + 0] * COORD_SCALE;
        const float ay = xa[i * 3 + 1] * COORD_SCALE;
        const float az = xa[i * 3 + 2] * COORD_SCALE;
        const float si = ex2(-0.5f * (ax * ax + ay * ay + az * az));
        const float bx = na[i * 3 + 0] * si;
        const float by = na[i * 3 + 1] * si;
        const float bz = na[i * 3 + 2] * si;
        px[t] = pack2(ax, ax);
        py[t] = pack2(ay, ay);
        pz[t] = pack2(az, az);
        nx[t] = pack2(bx, bx);
        ny[t] = pack2(by, by);
        nz[t] = pack2(bz, bz);
        acc[t] = 0ull;
    }

    // ---- j loop over TILE in JSUB-wide smem sub-tiles ----
    for (int j0 = tj * TILE; j0 < tj * TILE + TILE; j0 += JSUB) {
        __syncthreads();
        {
            const int j  = j0 + tid;
            const float qx = xb[j * 3 + 0] * COORD_SCALE;
            const float qy = xb[j * 3 + 1] * COORD_SCALE;
            const float qz = xb[j * 3 + 2] * COORD_SCALE;
            const float sj = ex2(-0.5f * (qx * qx + qy * qy + qz * qz));
            const float mx = nb[j * 3 + 0] * sj;
            const float my = nb[j * 3 + 1] * sj;
            const float mz = nb[j * 3 + 2] * sj;
            const int jp = tid >> 1;
            const int l  = tid & 1;
            float* base = (float*)&sb[jp * 3];
            base[0 + l]  = qx;  base[2 + l]  = qy;
            base[4 + l]  = qz;  base[6 + l]  = mx;
            base[8 + l]  = my;  base[10 + l] = mz;
        }
        __syncthreads();

        // software pipeline with a bumped pointer — LDS [ptr+0/16/32],
        // pointer advance is a single IADD3 on the ALU pipe (not IMAD/FMA pipe)
        const ulonglong2* jptr = (const ulonglong2*)sb;
        ulonglong2 c0 = jptr[0], c1 = jptr[1], c2 = jptr[2];
        #pragma unroll 4
        for (int it = 0; it < JSUB / 2; it++) {
            jptr += 3;
            const ulonglong2 n0 = jptr[0];   // pads make last prefetch safe
            const ulonglong2 n1 = jptr[1];
            const ulonglong2 n2 = jptr[2];

            // a-dots (both i chains)
            ull a0 = mul2(px[0], c0.x);
            ull a1 = mul2(px[1], c0.x);
            a0 = fma2(py[0], c0.y, a0);
            a1 = fma2(py[1], c0.y, a1);
            a0 = fma2(pz[0], c1.x, a0);
            a1 = fma2(pz[1], c1.x, a1);

            // issue all 4 EX2 back-to-back
            float a00, a01, a10, a11;
            unpack2(a0, a00, a01);
            unpack2(a1, a10, a11);
            const float e00 = ex2(a00);
            const float e01 = ex2(a01);
            const float e10 = ex2(a10);
            const float e11 = ex2(a11);

            // d-dots — independent work covering MUFU latency
            ull d0 = mul2(nx[0], c1.y);
            ull d1 = mul2(nx[1], c1.y);
            d0 = fma2(ny[0], c2.x, d0);
            d1 = fma2(ny[1], c2.x, d1);
            d0 = fma2(nz[0], c2.y, d0);
            d1 = fma2(nz[1], c2.y, d1);

            // combine: acc += (2^a * D')^2
            const ull e0 = pack2(e00, e01);
            const ull e1 = pack2(e10, e11);
            const ull t0 = mul2(e0, d0);
            const ull t1 = mul2(e1, d1);
            acc[0] = fma2(t0, t0, acc[0]);
            acc[1] = fma2(t1, t1, acc[1]);

            c0 = n0; c1 = n1; c2 = n2;
        }
    }

    // ---- block reduction (deterministic) ----
    float v = 0.0f;
    #pragma unroll
    for (int t = 0; t < ITILE; t++) {
        float a0, a1;
        unpack2(acc[t], a0, a1);
        v += a0 + a1;
    }
    #pragma unroll
    for (int o = 16; o > 0; o >>= 1)
        v += __shfl_xor_sync(0xffffffffu, v, o);
    if ((tid & 31) == 0) warpsum[tid >> 5] = v;
    __syncthreads();

    __shared__ bool is_last;
    if (tid == 0) {
        float s = 0.0f;
        #pragma unroll
        for (int k = 0; k < TPB / 32; k++) s += warpsum[k];
        const int blin = blockIdx.y * gridDim.x + blockIdx.x;
        g_partials[blin] = s * w;
        __threadfence();
        const unsigned int done = atomicAdd(&g_count, 1u);
        is_last = (done == (unsigned int)(NBLOCKS - 1));
    }
    __syncthreads();

    // ---- last block finalizes (fixed order => deterministic) ----
    if (is_last) {
        float r = 0.0f;
        for (int i = tid; i < NBLOCKS; i += TPB)
            r += __ldcg(&g_partials[i]);
        #pragma unroll
        for (int o = 16; o > 0; o >>= 1)
            r += __shfl_xor_sync(0xffffffffu, r, o);
        if ((tid & 31) == 0) warpsum[tid >> 5] = r;
        __syncthreads();
        if (tid == 0) {
            float s = 0.0f;
            #pragma unroll
            for (int k = 0; k < TPB / 32; k++) s += warpsum[k];
            out[0] = s;
            g_count = 0;   // reset for next graph replay
        }
    }
}

extern "C" void kernel_launch(void* const* d_in, const int* in_sizes, int n_in,
                              void* d_out, int out_size)
{
    const float* xyz1 = (const float*)d_in[0];
    const float* xyz2 = (const float*)d_in[1];
    const float* nor1 = (const float*)d_in[2];
    const float* nor2 = (const float*)d_in[3];

    dim3 grid(BPB, BATCH);
    varifold_fused<<<grid, TPB>>>(xyz1, xyz2, nor1, nor2, (float*)d_out);
}

// round 9
// speedup vs baseline: 1.0583x; 1.0583x over previous
#include <cuda_runtime.h>

#define NPTS    4096
#define BATCH   4
#define TPB     256
#define ITILE   2
#define TILE    512                     // square tile side
#define T       (NPTS / TILE)           // 8
#define NSYM    (T * (T + 1) / 2)       // 36
#define NCROSS  (T * T)                 // 64
#define TPB_PAIRS 136                   // tile-pairs per batch
#define TILES   (TPB_PAIRS * BATCH)     // 544 tiles total
#define JP_PER_TILE (TILE / 2)          // 256 j-pair columns per tile
#define JP_TOTAL (TILES * JP_PER_TILE)  // 139264
#define NBLK    592                     // 148 SMs x 4 blocks, uniformly resident
#define WIN     128                     // j-pairs per smem window (= 256 j)

// sqrt(log2(e)): p = x*SCALE  =>  p_i.p_j = log2(e) * x_i.x_j
#define COORD_SCALE 1.2011224087864498f

__device__ float g_partials[NBLK];
__device__ unsigned int g_count = 0;

typedef unsigned long long ull;

__device__ __forceinline__ ull pack2(float lo, float hi) {
    ull r;
    asm("mov.b64 %0, {%1, %2};" : "=l"(r) : "f"(lo), "f"(hi));
    return r;
}
__device__ __forceinline__ void unpack2(ull v, float& lo, float& hi) {
    asm("mov.b64 {%0, %1}, %2;" : "=f"(lo), "=f"(hi) : "l"(v));
}
__device__ __forceinline__ ull fma2(ull a, ull b, ull c) {
    ull d;
    asm("fma.rn.f32x2 %0, %1, %2, %3;" : "=l"(d) : "l"(a), "l"(b), "l"(c));
    return d;
}
__device__ __forceinline__ ull mul2(ull a, ull b) {
    ull d;
    asm("mul.rn.f32x2 %0, %1, %2;" : "=l"(d) : "l"(a), "l"(b));
    return d;
}
__device__ __forceinline__ float ex2(float x) {
    float r;
    asm("ex2.approx.ftz.f32 %0, %1;" : "=f"(r) : "f"(x));
    return r;
}

// j-window layout: per j-pair, 3 float4s (48B):
//   [0]={qx_e,qx_o,qy_e,qy_o} [1]={qz_e,qz_o,mx_e,mx_o} [2]={my_e,my_o,mz_e,mz_o}
// m = n_j * 2^{c_j} (exponent constants folded into normals)

__global__ void __launch_bounds__(TPB, 4)
varifold_fused(const float* __restrict__ xyz1,
               const float* __restrict__ xyz2,
               const float* __restrict__ nor1,
               const float* __restrict__ nor2,
               float* __restrict__ out)
{
    // +3 pad float4s so pipeline prefetch past the last pair is safe
    __shared__ __align__(16) float4 sb[WIN * 3 + 3];
    __shared__ float warpsum[TPB / 32];

    const int tid = threadIdx.x;
    const int bid = blockIdx.x;

    // balanced flat partition of j-pair columns
    const ull p0 = ((ull)bid * JP_TOTAL) / NBLK;
    const ull p1 = ((ull)(bid + 1) * JP_TOTAL) / NBLK;

    float vsum = 0.0f;   // per-thread weighted sum over segments

    ull p = p0;
    while (p < p1) {
        const int tile = (int)(p >> 8);            // 256 j-pairs per tile
        const int pj0  = (int)(p & 255);
        const int rem  = (int)(p1 - p);
        const int pj1  = (pj0 + rem < JP_PER_TILE) ? pj0 + rem : JP_PER_TILE;

        // ---- decode tile -> (batch, term, ti, tj, weight) ----
        const int bt  = tile / TPB_PAIRS;
        int idx = tile - bt * TPB_PAIRS;
        int term, ti, tj;
        float w;
        if (idx < 2 * NSYM) {
            term = (idx < NSYM) ? 0 : 1;
            int k = (idx < NSYM) ? idx : idx - NSYM;
            ti = 0;
            while (k >= T - ti) { k -= T - ti; ti++; }
            tj = ti + k;
            w = (ti == tj) ? 1.0f : 2.0f;          // symmetric: off-diag x2
        } else {
            term = 2;
            const int q = idx - 2 * NSYM;
            ti = q >> 3;                           // T == 8
            tj = q & (T - 1);
            w = -2.0f;
        }

        const float* xa; const float* xb; const float* na; const float* nb;
        if (term == 0)      { xa = xyz1; xb = xyz1; na = nor1; nb = nor1; }
        else if (term == 1) { xa = xyz2; xb = xyz2; na = nor2; nb = nor2; }
        else                { xa = xyz1; xb = xyz2; na = nor1; nb = nor2; }
        const long boff = (long)bt * NPTS * 3;
        xa += boff; xb += boff; na += boff; nb += boff;

        // ---- register-resident i points: p_i, n'_i = n_i * 2^{c_i} ----
        ull px[ITILE], py[ITILE], pz[ITILE];
        ull nx[ITILE], ny[ITILE], nz[ITILE], acc[ITILE];
        #pragma unroll
        for (int t = 0; t < ITILE; t++) {
            const int i = ti * TILE + t * TPB + tid;
            const float ax = xa[i * 3 + 0] * COORD_SCALE;
            const float ay = xa[i * 3 + 1] * COORD_SCALE;
            const float az = xa[i * 3 + 2] * COORD_SCALE;
            const float si = ex2(-0.5f * (ax * ax + ay * ay + az * az));
            const float bx = na[i * 3 + 0] * si;
            const float by = na[i * 3 + 1] * si;
            const float bz = na[i * 3 + 2] * si;
            px[t] = pack2(ax, ax);
            py[t] = pack2(ay, ay);
            pz[t] = pack2(az, az);
            nx[t] = pack2(bx, bx);
            ny[t] = pack2(by, by);
            nz[t] = pack2(bz, bz);
            acc[t] = 0ull;
        }

        // ---- j windows of WIN pairs covering [pj0, pj1) ----
        for (int w0 = pj0 & ~(WIN - 1); w0 < pj1; w0 += WIN) {
            __syncthreads();
            {
                const int j  = tj * TILE + w0 * 2 + tid;
                const float qx = xb[j * 3 + 0] * COORD_SCALE;
                const float qy = xb[j * 3 + 1] * COORD_SCALE;
                const float qz = xb[j * 3 + 2] * COORD_SCALE;
                const float sj = ex2(-0.5f * (qx * qx + qy * qy + qz * qz));
                const float mx = nb[j * 3 + 0] * sj;
                const float my = nb[j * 3 + 1] * sj;
                const float mz = nb[j * 3 + 2] * sj;
                const int jp = tid >> 1;
                const int l  = tid & 1;
                float* base = (float*)&sb[jp * 3];
                base[0 + l]  = qx;  base[2 + l]  = qy;
                base[4 + l]  = qz;  base[6 + l]  = mx;
                base[8 + l]  = my;  base[10 + l] = mz;
            }
            __syncthreads();

            const int lo = (pj0 > w0 ? pj0 : w0) - w0;
            const int hi = (pj1 < w0 + WIN ? pj1 : w0 + WIN) - w0;
            const int n  = hi - lo;

            const ulonglong2* jptr = ((const ulonglong2*)sb) + 3 * lo;
            ulonglong2 c0 = jptr[0], c1 = jptr[1], c2 = jptr[2];
            #pragma unroll 4
            for (int it = 0; it < n; it++) {
                jptr += 3;
                const ulonglong2 n0 = jptr[0];   // pad makes last prefetch safe
                const ulonglong2 n1 = jptr[1];
                const ulonglong2 n2 = jptr[2];

                // a-dots (both i chains)
                ull a0 = mul2(px[0], c0.x);
                ull a1 = mul2(px[1], c0.x);
                a0 = fma2(py[0], c0.y, a0);
                a1 = fma2(py[1], c0.y, a1);
                a0 = fma2(pz[0], c1.x, a0);
                a1 = fma2(pz[1], c1.x, a1);

                // 4 EX2 back-to-back
                float a00, a01, a10, a11;
                unpack2(a0, a00, a01);
                unpack2(a1, a10, a11);
                const float e00 = ex2(a00);
                const float e01 = ex2(a01);
                const float e10 = ex2(a10);
                const float e11 = ex2(a11);

                // d-dots — cover MUFU latency
                ull d0 = mul2(nx[0], c1.y);
                ull d1 = mul2(nx[1], c1.y);
                d0 = fma2(ny[0], c2.x, d0);
                d1 = fma2(ny[1], c2.x, d1);
                d0 = fma2(nz[0], c2.y, d0);
                d1 = fma2(nz[1], c2.y, d1);

                // acc += (2^a * D')^2
                const ull e0 = pack2(e00, e01);
                const ull e1 = pack2(e10, e11);
                const ull t0 = mul2(e0, d0);
                const ull t1 = mul2(e1, d1);
                acc[0] = fma2(t0, t0, acc[0]);
                acc[1] = fma2(t1, t1, acc[1]);

                c0 = n0; c1 = n1; c2 = n2;
            }
        }

        // fold segment into weighted per-thread sum
        #pragma unroll
        for (int t = 0; t < ITILE; t++) {
            float a0, a1;
            unpack2(acc[t], a0, a1);
            vsum += w * (a0 + a1);
        }

        p += (ull)(pj1 - pj0);
    }

    // ---- block reduction (deterministic) ----
    float v = vsum;
    #pragma unroll
    for (int o = 16; o > 0; o >>= 1)
        v += __shfl_xor_sync(0xffffffffu, v, o);
    if ((tid & 31) == 0) warpsum[tid >> 5] = v;
    __syncthreads();

    __shared__ bool is_last;
    if (tid == 0) {
        float s = 0.0f;
        #pragma unroll
        for (int k = 0; k < TPB / 32; k++) s += warpsum[k];
        g_partials[bid] = s;
        __threadfence();
        const unsigned int done = atomicAdd(&g_count, 1u);
        is_last = (done == (unsigned int)(NBLK - 1));
    }
    __syncthreads();

    // ---- last block finalizes (fixed order => deterministic) ----
    if (is_last) {
        float r = 0.0f;
        for (int i = tid; i < NBLK; i += TPB)
            r += __ldcg(&g_partials[i]);
        #pragma unroll
        for (int o = 16; o > 0; o >>= 1)
            r += __shfl_xor_sync(0xffffffffu, r, o);
        if ((tid & 31) == 0) warpsum[tid >> 5] = r;
        __syncthreads();
        if (tid == 0) {
            float s = 0.0f;
            #pragma unroll
            for (int k = 0; k < TPB / 32; k++) s += warpsum[k];
            out[0] = s;
            g_count = 0;   // reset for next graph replay
        }
    }
}

extern "C" void kernel_launch(void* const* d_in, const int* in_sizes, int n_in,
                              void* d_out, int out_size)
{
    const float* xyz1 = (const float*)d_in[0];
    const float* xyz2 = (const float*)d_in[1];
    const float* nor1 = (const float*)d_in[2];
    const float* nor2 = (const float*)d_in[3];

    varifold_fused<<<NBLK, TPB>>>(xyz1, xyz2, nor1, nor2, (float*)d_out);
}